// round 3
// baseline (speedup 1.0000x reference)
#include <cuda_runtime.h>

// ---------------- problem constants ----------------
constexpr int NN = 50000;      // nodes
constexpr int NE = 800000;     // edges
constexpr int IND = 64;        // input dim
constexpr int HD = 128;        // hidden dim
constexpr int NG = 1024;       // graphs
constexpr float SLOPE = 0.01f; // leaky relu

// ---------------- scratch buffers (device globals; no allocs) ----------------
__device__ __align__(256) float g_agg[(size_t)NN * HD];
__device__ __align__(256) float g_h[(size_t)NN * HD];
__device__ __align__(256) float g_res[(size_t)NN * HD];
__device__ __align__(256) float g_sums[(size_t)NG * HD];
__device__ __align__(256) float g_cnt[NG];
__device__ __align__(256) int   g_ei[2 * NE];   // int32 src (first NE) / dst (last NE)
__device__ __align__(256) int   g_batch[NN];
__device__ int g_is64;

// ---------------- tiling config ----------------
constexpr int BM = 64;   // rows per block tile
constexpr int BK = 16;   // k-chunk

// ============================================================
// index dtype detection + conversion
// Reference declares int64 but JAX default (x64 off) yields int32.
// If the raw words at odd positions are ALL zero over 4096 entries,
// data is int64 (values < 2^31, nonneg); otherwise int32.
// ============================================================
__global__ void detect_dtype(const int* __restrict__ raw) {
    __shared__ int s_any;
    if (threadIdx.x == 0) s_any = 0;
    __syncthreads();
    int bad = 0;
    for (int i = threadIdx.x; i < 4096; i += blockDim.x)
        bad |= raw[2 * i + 1];
    if (bad) atomicOr(&s_any, 1);
    __syncthreads();
    if (threadIdx.x == 0) g_is64 = (s_any == 0) ? 1 : 0;
}

__global__ void convert_idx(const void* __restrict__ raw, int* __restrict__ out, int n) {
    int i = blockIdx.x * blockDim.x + threadIdx.x;
    if (i >= n) return;
    if (g_is64) out[i] = (int)((const long long*)raw)[i];
    else        out[i] = ((const int*)raw)[i];
}

// ============================================================
// copy kernel
// ============================================================
__global__ void copy_f4(const float* __restrict__ src, float* __restrict__ dst, int n4) {
    int i = blockIdx.x * blockDim.x + threadIdx.x;
    if (i < n4) ((float4*)dst)[i] = ((const float4*)src)[i];
}

// ============================================================
// scatter: g_agg[dst,:] += X[src,:]   (D = 64 or 128)
// one thread per (edge, float4-chunk); vector L2 reduction
// ============================================================
template<int D>
__global__ void scatter_add(const float* __restrict__ X) {
    constexpr int F4 = D / 4;
    long long gid = (long long)blockIdx.x * blockDim.x + threadIdx.x;
    int e = (int)(gid / F4);
    int c = (int)(gid % F4);
    if (e >= NE) return;
    int s = __ldg(&g_ei[e]);
    int d = __ldg(&g_ei[NE + e]);
    float4 v = __ldg((const float4*)(X + (size_t)s * D) + c);
    float* p = g_agg + (size_t)d * D + (size_t)c * 4;
    asm volatile("red.global.add.v4.f32 [%0], {%1,%2,%3,%4};"
                 :: "l"(p), "f"(v.x), "f"(v.y), "f"(v.z), "f"(v.w) : "memory");
}

// ============================================================
// plain GEMM: Out[N,128] = A[N,K1] @ W[K1,128]   (residual projection)
// ============================================================
template<int K1>
__global__ void __launch_bounds__(256)
gemm_plain(const float* __restrict__ A, const float* __restrict__ W, float* __restrict__ Out) {
    __shared__ float sA[BM][BK + 1];
    __shared__ float sW[BK][HD];
    int r0 = blockIdx.x * BM;
    int tid = threadIdx.x;
    int ty = tid >> 4, tx = tid & 15;
    float acc[4][8];
#pragma unroll
    for (int i = 0; i < 4; i++)
#pragma unroll
        for (int j = 0; j < 8; j++) acc[i][j] = 0.f;

    for (int kb = 0; kb < K1; kb += BK) {
        {
            int row = tid >> 2;
            int c4 = tid & 3;
            int gr = r0 + row;
            float4 v = make_float4(0.f, 0.f, 0.f, 0.f);
            if (gr < NN) v = __ldg((const float4*)(A + (size_t)gr * K1 + kb) + c4);
            sA[row][c4 * 4 + 0] = v.x; sA[row][c4 * 4 + 1] = v.y;
            sA[row][c4 * 4 + 2] = v.z; sA[row][c4 * 4 + 3] = v.w;
        }
        {
#pragma unroll
            for (int u = 0; u < 2; u++) {
                int t = tid + u * 256;
                int k = t >> 5;
                int c4 = t & 31;
                float4 v = __ldg((const float4*)(W + (size_t)(kb + k) * HD) + c4);
                *((float4*)&sW[k][c4 * 4]) = v;
            }
        }
        __syncthreads();
#pragma unroll
        for (int k = 0; k < BK; k++) {
            float a[4], w[8];
#pragma unroll
            for (int i = 0; i < 4; i++) a[i] = sA[ty * 4 + i][k];
#pragma unroll
            for (int j = 0; j < 8; j++) w[j] = sW[k][tx * 8 + j];
#pragma unroll
            for (int i = 0; i < 4; i++)
#pragma unroll
                for (int j = 0; j < 8; j++) acc[i][j] = fmaf(a[i], w[j], acc[i][j]);
        }
        __syncthreads();
    }
#pragma unroll
    for (int i = 0; i < 4; i++) {
        int gr = r0 + ty * 4 + i;
        if (gr < NN) {
#pragma unroll
            for (int j = 0; j < 8; j += 4) {
                float4 v = make_float4(acc[i][j], acc[i][j + 1], acc[i][j + 2], acc[i][j + 3]);
                *((float4*)(Out + (size_t)gr * HD + tx * 8 + j)) = v;
            }
        }
    }
}

// ============================================================
// fused GIN MLP: Out = relu( relu(A@W1 + b1) @ W2 + b2 + Res )
// ============================================================
template<int K1, bool DUP>
__global__ void __launch_bounds__(256)
gin_mlp(const float* __restrict__ A,
        const float* __restrict__ W1, const float* __restrict__ b1,
        const float* __restrict__ W2, const float* __restrict__ b2,
        const float* __restrict__ Res,
        float* __restrict__ Out, float* __restrict__ Out2) {
    __shared__ float sA[BM][BK + 1];
    __shared__ float sW[BK][HD];
    __shared__ float sT[BM][HD + 4];
    int r0 = blockIdx.x * BM;
    int tid = threadIdx.x;
    int ty = tid >> 4, tx = tid & 15;

    float acc[4][8];
#pragma unroll
    for (int i = 0; i < 4; i++)
#pragma unroll
        for (int j = 0; j < 8; j++) acc[i][j] = 0.f;

    // ---- phase 1: t = relu(A @ W1 + b1) ----
    for (int kb = 0; kb < K1; kb += BK) {
        {
            int row = tid >> 2;
            int c4 = tid & 3;
            int gr = r0 + row;
            float4 v = make_float4(0.f, 0.f, 0.f, 0.f);
            if (gr < NN) v = __ldg((const float4*)(A + (size_t)gr * K1 + kb) + c4);
            sA[row][c4 * 4 + 0] = v.x; sA[row][c4 * 4 + 1] = v.y;
            sA[row][c4 * 4 + 2] = v.z; sA[row][c4 * 4 + 3] = v.w;
        }
        {
#pragma unroll
            for (int u = 0; u < 2; u++) {
                int t = tid + u * 256;
                int k = t >> 5;
                int c4 = t & 31;
                float4 v = __ldg((const float4*)(W1 + (size_t)(kb + k) * HD) + c4);
                *((float4*)&sW[k][c4 * 4]) = v;
            }
        }
        __syncthreads();
#pragma unroll
        for (int k = 0; k < BK; k++) {
            float a[4], w[8];
#pragma unroll
            for (int i = 0; i < 4; i++) a[i] = sA[ty * 4 + i][k];
#pragma unroll
            for (int j = 0; j < 8; j++) w[j] = sW[k][tx * 8 + j];
#pragma unroll
            for (int i = 0; i < 4; i++)
#pragma unroll
                for (int j = 0; j < 8; j++) acc[i][j] = fmaf(a[i], w[j], acc[i][j]);
        }
        __syncthreads();
    }
    {
        float bb[8];
#pragma unroll
        for (int j = 0; j < 8; j++) bb[j] = __ldg(&b1[tx * 8 + j]);
#pragma unroll
        for (int i = 0; i < 4; i++)
#pragma unroll
            for (int j = 0; j < 8; j++)
                sT[ty * 4 + i][tx * 8 + j] = fmaxf(acc[i][j] + bb[j], 0.f);
    }
    __syncthreads();

    // ---- phase 2: out = relu(t @ W2 + b2 + res) ----
    float acc2[4][8];
#pragma unroll
    for (int i = 0; i < 4; i++)
#pragma unroll
        for (int j = 0; j < 8; j++) acc2[i][j] = 0.f;

    for (int kb = 0; kb < HD; kb += BK) {
        {
#pragma unroll
            for (int u = 0; u < 2; u++) {
                int t = tid + u * 256;
                int k = t >> 5;
                int c4 = t & 31;
                float4 v = __ldg((const float4*)(W2 + (size_t)(kb + k) * HD) + c4);
                *((float4*)&sW[k][c4 * 4]) = v;
            }
        }
        __syncthreads();
#pragma unroll
        for (int k = 0; k < BK; k++) {
            float a[4], w[8];
#pragma unroll
            for (int i = 0; i < 4; i++) a[i] = sT[ty * 4 + i][kb + k];
#pragma unroll
            for (int j = 0; j < 8; j++) w[j] = sW[k][tx * 8 + j];
#pragma unroll
            for (int i = 0; i < 4; i++)
#pragma unroll
                for (int j = 0; j < 8; j++) acc2[i][j] = fmaf(a[i], w[j], acc2[i][j]);
        }
        __syncthreads();
    }

    {
        float bb[8];
#pragma unroll
        for (int j = 0; j < 8; j++) bb[j] = __ldg(&b2[tx * 8 + j]);
#pragma unroll
        for (int i = 0; i < 4; i++) {
            int gr = r0 + ty * 4 + i;
            if (gr < NN) {
#pragma unroll
                for (int j = 0; j < 8; j += 4) {
                    float4 rv = __ldg((const float4*)(Res + (size_t)gr * HD + tx * 8 + j));
                    float4 o;
                    o.x = fmaxf(acc2[i][j + 0] + bb[j + 0] + rv.x, 0.f);
                    o.y = fmaxf(acc2[i][j + 1] + bb[j + 1] + rv.y, 0.f);
                    o.z = fmaxf(acc2[i][j + 2] + bb[j + 2] + rv.z, 0.f);
                    o.w = fmaxf(acc2[i][j + 3] + bb[j + 3] + rv.w, 0.f);
                    *((float4*)(Out + (size_t)gr * HD + tx * 8 + j)) = o;
                    if (DUP) *((float4*)(Out2 + (size_t)gr * HD + tx * 8 + j)) = o;
                }
            }
        }
    }
}

// ============================================================
// pooling
// ============================================================
__global__ void zero_pool() {
    int i = blockIdx.x * blockDim.x + threadIdx.x;
    if (i < NG * HD) g_sums[i] = 0.f;
    if (i < NG) g_cnt[i] = 0.f;
}

__global__ void pool_accum() {
    long long gid = (long long)blockIdx.x * blockDim.x + threadIdx.x;
    int node = (int)(gid >> 5);
    int c = (int)(gid & 31);
    if (node >= NN) return;
    int b = __ldg(&g_batch[node]);
    float4 v = __ldg((const float4*)(g_h + (size_t)node * HD) + c);
    float* p = g_sums + (size_t)b * HD + (size_t)c * 4;
    asm volatile("red.global.add.v4.f32 [%0], {%1,%2,%3,%4};"
                 :: "l"(p), "f"(v.x), "f"(v.y), "f"(v.z), "f"(v.w) : "memory");
    if (c == 0) atomicAdd(&g_cnt[b], 1.0f);
}

// ============================================================
// fc head
// ============================================================
__global__ void __launch_bounds__(128)
head_kernel(const float* __restrict__ fW1, const float* __restrict__ fb1,
            const float* __restrict__ fW2, const float* __restrict__ fb2,
            float* __restrict__ out) {
    int g = blockIdx.x;
    int t = threadIdx.x;
    __shared__ float sp[HD];
    __shared__ float red[HD];
    float cnt = g_cnt[g];
    float inv = 1.0f / fmaxf(cnt, 1.0f);
    sp[t] = g_sums[(size_t)g * HD + t] * inv;
    __syncthreads();
    float acc = 0.f;
#pragma unroll 8
    for (int k = 0; k < HD; k++) acc = fmaf(sp[k], __ldg(&fW1[(size_t)k * HD + t]), acc);
    float hh = acc + __ldg(&fb1[t]);
    hh = (hh > 0.f) ? hh : hh * SLOPE;
    red[t] = hh * __ldg(&fW2[t]);
    __syncthreads();
    for (int s = 64; s > 0; s >>= 1) {
        if (t < s) red[t] += red[t + s];
        __syncthreads();
    }
    if (t == 0) out[g] = red[0] + __ldg(&fb2[0]);
}

// ============================================================
// launch
// ============================================================
extern "C" void kernel_launch(void* const* d_in, const int* in_sizes, int n_in,
                              void* d_out, int out_size) {
    const float* x     = (const float*)d_in[0];
    const void*  ei    = d_in[1];
    const void*  batch = d_in[2];
    const float* l0_W1   = (const float*)d_in[3];
    const float* l0_b1   = (const float*)d_in[4];
    const float* l0_W2   = (const float*)d_in[5];
    const float* l0_b2   = (const float*)d_in[6];
    const float* l0_Wres = (const float*)d_in[7];
    const float* Ws1 = (const float*)d_in[8];
    const float* bs1 = (const float*)d_in[9];
    const float* Ws2 = (const float*)d_in[10];
    const float* bs2 = (const float*)d_in[11];
    const float* fW1 = (const float*)d_in[12];
    const float* fb1 = (const float*)d_in[13];
    const float* fW2 = (const float*)d_in[14];
    const float* fb2 = (const float*)d_in[15];
    float* out = (float*)d_out;

    float *agg, *h, *res;
    int *eiI, *batchI;
    cudaGetSymbolAddress((void**)&agg, g_agg);
    cudaGetSymbolAddress((void**)&h, g_h);
    cudaGetSymbolAddress((void**)&res, g_res);
    cudaGetSymbolAddress((void**)&eiI, g_ei);
    cudaGetSymbolAddress((void**)&batchI, g_batch);

    // ---- index dtype detection + conversion ----
    detect_dtype<<<1, 256>>>((const int*)ei);
    convert_idx<<<(2 * NE + 255) / 256, 256>>>(ei, eiI, 2 * NE);
    convert_idx<<<(NN + 255) / 256, 256>>>(batch, batchI, NN);

    const int gemm_blocks = (NN + BM - 1) / BM;   // 782

    // ---- layer 0 (64 -> 128, projected residual) ----
    copy_f4<<<(NN * IND / 4 + 255) / 256, 256>>>(x, agg, NN * IND / 4);
    scatter_add<IND><<<(NE * (IND / 4) + 255) / 256, 256>>>(x);
    gemm_plain<IND><<<gemm_blocks, 256>>>(x, l0_Wres, res);
    gin_mlp<IND, false><<<gemm_blocks, 256>>>(agg, l0_W1, l0_b1, l0_W2, l0_b2, res, h, nullptr);

    // ---- layers 1..3 (128 -> 128, identity residual) ----
    copy_f4<<<(NN * HD / 4 + 255) / 256, 256>>>(h, agg, NN * HD / 4);
    for (int i = 0; i < 3; i++) {
        scatter_add<HD><<<(NE * (HD / 4) + 255) / 256, 256>>>(h);
        const float* W1 = Ws1 + (size_t)i * HD * HD;
        const float* B1 = bs1 + (size_t)i * HD;
        const float* W2 = Ws2 + (size_t)i * HD * HD;
        const float* B2 = bs2 + (size_t)i * HD;
        if (i < 2)
            gin_mlp<HD, true><<<gemm_blocks, 256>>>(agg, W1, B1, W2, B2, h, h, agg);
        else
            gin_mlp<HD, false><<<gemm_blocks, 256>>>(agg, W1, B1, W2, B2, h, h, nullptr);
    }

    // ---- mean pool + head ----
    zero_pool<<<(NG * HD + 255) / 256, 256>>>();
    pool_accum<<<(NN * 32 + 255) / 256, 256>>>();
    head_kernel<<<NG, 128>>>(fW1, fb1, fW2, fb2, out);
}

// round 5
// speedup vs baseline: 1.0831x; 1.0831x over previous
#include <cuda_runtime.h>
#include <mma.h>
#include <cstdint>

using namespace nvcuda;

// ---------------- problem constants ----------------
constexpr int NN = 50000;
constexpr int NE = 800000;
constexpr int IND = 64;
constexpr int HD = 128;
constexpr int NG = 1024;
constexpr float SLOPE = 0.01f;

constexpr int LDA = 132;   // smem leading dim (multiple of 4, skewed)

// ---------------- scratch (device globals) ----------------
__device__ __align__(256) float g_agg[(size_t)NN * HD];
__device__ __align__(256) float g_h[(size_t)NN * HD];
__device__ __align__(256) float g_sums[(size_t)NG * HD];
__device__ __align__(256) float g_cnt[NG];
__device__ __align__(256) int   g_ei[2 * NE];
__device__ __align__(256) int   g_batch[NN];
__device__ int g_is64;

// ============================================================
// index dtype detection + conversion
// ============================================================
__global__ void detect_dtype(const int* __restrict__ raw) {
    __shared__ int s_any;
    if (threadIdx.x == 0) s_any = 0;
    __syncthreads();
    int bad = 0;
    for (int i = threadIdx.x; i < 4096; i += blockDim.x) bad |= raw[2 * i + 1];
    if (bad) atomicOr(&s_any, 1);
    __syncthreads();
    if (threadIdx.x == 0) g_is64 = (s_any == 0) ? 1 : 0;
}
__global__ void convert_idx(const void* __restrict__ raw, int* __restrict__ out, int n) {
    int i = blockIdx.x * blockDim.x + threadIdx.x;
    if (i >= n) return;
    if (g_is64) out[i] = (int)((const long long*)raw)[i];
    else        out[i] = ((const int*)raw)[i];
}

// ============================================================
// copy
// ============================================================
__global__ void copy_f4(const float* __restrict__ src, float* __restrict__ dst, int n4) {
    int i = blockIdx.x * blockDim.x + threadIdx.x;
    if (i < n4) ((float4*)dst)[i] = ((const float4*)src)[i];
}

// ============================================================
// scatter: g_agg[dst,:] += X[src,:]
// ============================================================
template<int D>
__global__ void scatter_add(const float* __restrict__ X) {
    constexpr int F4 = D / 4;
    long long gid = (long long)blockIdx.x * blockDim.x + threadIdx.x;
    int e = (int)(gid / F4);
    int c = (int)(gid % F4);
    if (e >= NE) return;
    int s = __ldg(&g_ei[e]);
    int d = __ldg(&g_ei[NE + e]);
    float4 v = __ldg((const float4*)(X + (size_t)s * D) + c);
    float* p = g_agg + (size_t)d * D + (size_t)c * 4;
    asm volatile("red.global.add.v4.f32 [%0], {%1,%2,%3,%4};"
                 :: "l"(p), "f"(v.x), "f"(v.y), "f"(v.z), "f"(v.w) : "memory");
}

// ============================================================
// fused GIN MLP on warp tensor cores (wmma tf32):
//   Out = relu( relu(A@W1 + b1) @ W2 + b2 + Res )
// L0: Res = x @ Wres computed on-chip into sR.
// Block: 256 threads = 8 warps; warp w owns output rows [16w,16w+16).
// ============================================================
template<int K1, bool L0, bool DUP>
__global__ void __launch_bounds__(256)
gin_wmma(const float* __restrict__ A,
         const float* __restrict__ W1, const float* __restrict__ b1,
         const float* __restrict__ W2, const float* __restrict__ b2,
         const float* __restrict__ Wres,
         const float* __restrict__ XorRes,   // L0: x ; else residual source
         float* __restrict__ Out, float* __restrict__ Out2) {
    extern __shared__ float sm[];
    float* sA = sm;                     // 128 x LDA (A tile, then T tile)
    float* sW = sm + 128 * LDA;         // 128 x LDA (weights, then D tile)
    float* sR = sm + 2 * 128 * LDA;     // 128 x LDA (L0 residual)

    int tid = threadIdx.x;
    int wid = tid >> 5;
    int r0 = blockIdx.x * 128;

    wmma::fragment<wmma::accumulator, 16, 16, 8, float> acc[8];

    // ---- tile loaders (fp32, raw; tf32 conversion happens in-fragment) ----
    auto loadA = [&](const float* __restrict__ src, int K) {
        int n4 = 128 * (K >> 2);
        int c4n = K >> 2;
        for (int idx = tid; idx < n4; idx += 256) {
            int row = idx / c4n, c4 = idx % c4n;
            float4 v = make_float4(0.f, 0.f, 0.f, 0.f);
            if (r0 + row < NN) v = __ldg((const float4*)(src + (size_t)(r0 + row) * K) + c4);
            *(float4*)(sA + row * LDA + c4 * 4) = v;
        }
    };
    auto loadW = [&](const float* __restrict__ src, int K) {
        int n4 = K * 32;
        for (int idx = tid; idx < n4; idx += 256) {
            int row = idx >> 5, c4 = idx & 31;
            float4 v = __ldg((const float4*)(src + (size_t)row * 128) + c4);
            *(float4*)(sW + row * LDA + c4 * 4) = v;
        }
    };
    auto mmaPhase = [&](int ksteps) {
#pragma unroll
        for (int n = 0; n < 8; n++) wmma::fill_fragment(acc[n], 0.f);
        for (int k = 0; k < ksteps; k++) {
            wmma::fragment<wmma::matrix_a, 16, 16, 8, wmma::precision::tf32, wmma::row_major> af;
            wmma::load_matrix_sync(af, sA + wid * 16 * LDA + k * 8, LDA);
#pragma unroll
            for (int i = 0; i < af.num_elements; i++) af.x[i] = wmma::__float_to_tf32(af.x[i]);
#pragma unroll
            for (int n = 0; n < 8; n++) {
                wmma::fragment<wmma::matrix_b, 16, 16, 8, wmma::precision::tf32, wmma::row_major> bf;
                wmma::load_matrix_sync(bf, sW + k * 8 * LDA + n * 16, LDA);
#pragma unroll
                for (int i = 0; i < bf.num_elements; i++) bf.x[i] = wmma::__float_to_tf32(bf.x[i]);
                wmma::mma_sync(acc[n], af, bf, acc[n]);
            }
        }
    };

    // ---- L0: residual projection R = x @ Wres -> sR ----
    if (L0) {
        loadA(XorRes, 64);
        loadW(Wres, 64);
        __syncthreads();
        mmaPhase(8);
#pragma unroll
        for (int n = 0; n < 8; n++)
            wmma::store_matrix_sync(sR + wid * 16 * LDA + n * 16, acc[n], LDA, wmma::mem_row_major);
        __syncthreads();   // all mma reads of sA/sW done before reload
    }

    // ---- phase 1: T = relu(A @ W1 + b1) ----
    loadA(A, K1);
    loadW(W1, K1);
    __syncthreads();
    mmaPhase(K1 / 8);
    // store T into sA: each warp writes only its own 16 rows (the same rows it read)
#pragma unroll
    for (int n = 0; n < 8; n++)
        wmma::store_matrix_sync(sA + wid * 16 * LDA + n * 16, acc[n], LDA, wmma::mem_row_major);
    __syncthreads();
    // relu + bias (elementwise on T)
    for (int idx = tid; idx < 128 * 128; idx += 256) {
        int row = idx >> 7, col = idx & 127;
        float* p = sA + row * LDA + col;
        *p = fmaxf(*p + __ldg(&b1[col]), 0.f);
    }
    __syncthreads();

    // ---- phase 2: D = T @ W2 ----
    loadW(W2, 128);
    __syncthreads();
    mmaPhase(16);
    __syncthreads();   // all warps done reading sW before overwrite
#pragma unroll
    for (int n = 0; n < 8; n++)
        wmma::store_matrix_sync(sW + wid * 16 * LDA + n * 16, acc[n], LDA, wmma::mem_row_major);
    __syncthreads();

    // ---- epilogue: Out = relu(D + b2 + Res) ----
    for (int idx = tid; idx < 128 * 32; idx += 256) {
        int row = idx >> 5, c4 = idx & 31;
        int gr = r0 + row;
        if (gr >= NN) continue;
        float4 d = *(float4*)(sW + row * LDA + c4 * 4);
        float4 res4;
        if (L0) res4 = *(float4*)(sR + row * LDA + c4 * 4);
        else    res4 = __ldg((const float4*)(XorRes + (size_t)gr * HD) + c4);
        int col = c4 * 4;
        float4 o;
        o.x = fmaxf(d.x + __ldg(&b2[col + 0]) + res4.x, 0.f);
        o.y = fmaxf(d.y + __ldg(&b2[col + 1]) + res4.y, 0.f);
        o.z = fmaxf(d.z + __ldg(&b2[col + 2]) + res4.z, 0.f);
        o.w = fmaxf(d.w + __ldg(&b2[col + 3]) + res4.w, 0.f);
        *((float4*)(Out + (size_t)gr * HD) + c4) = o;
        if (DUP) *((float4*)(Out2 + (size_t)gr * HD) + c4) = o;
    }
}

// ============================================================
// pooling + head
// ============================================================
__global__ void zero_pool() {
    int i = blockIdx.x * blockDim.x + threadIdx.x;
    if (i < NG * HD) g_sums[i] = 0.f;
    if (i < NG) g_cnt[i] = 0.f;
}
__global__ void pool_accum() {
    long long gid = (long long)blockIdx.x * blockDim.x + threadIdx.x;
    int node = (int)(gid >> 5);
    int c = (int)(gid & 31);
    if (node >= NN) return;
    int b = __ldg(&g_batch[node]);
    float4 v = __ldg((const float4*)(g_h + (size_t)node * HD) + c);
    float* p = g_sums + (size_t)b * HD + (size_t)c * 4;
    asm volatile("red.global.add.v4.f32 [%0], {%1,%2,%3,%4};"
                 :: "l"(p), "f"(v.x), "f"(v.y), "f"(v.z), "f"(v.w) : "memory");
    if (c == 0) atomicAdd(&g_cnt[b], 1.0f);
}
__global__ void __launch_bounds__(128)
head_kernel(const float* __restrict__ fW1, const float* __restrict__ fb1,
            const float* __restrict__ fW2, const float* __restrict__ fb2,
            float* __restrict__ out) {
    int g = blockIdx.x;
    int t = threadIdx.x;
    __shared__ float sp[HD];
    __shared__ float red[HD];
    float inv = 1.0f / fmaxf(g_cnt[g], 1.0f);
    sp[t] = g_sums[(size_t)g * HD + t] * inv;
    __syncthreads();
    float acc = 0.f;
#pragma unroll 8
    for (int k = 0; k < HD; k++) acc = fmaf(sp[k], __ldg(&fW1[(size_t)k * HD + t]), acc);
    float hh = acc + __ldg(&fb1[t]);
    hh = (hh > 0.f) ? hh : hh * SLOPE;
    red[t] = hh * __ldg(&fW2[t]);
    __syncthreads();
    for (int s = 64; s > 0; s >>= 1) {
        if (t < s) red[t] += red[t + s];
        __syncthreads();
    }
    if (t == 0) out[g] = red[0] + __ldg(&fb2[0]);
}

// ============================================================
// launch
// ============================================================
extern "C" void kernel_launch(void* const* d_in, const int* in_sizes, int n_in,
                              void* d_out, int out_size) {
    const float* x     = (const float*)d_in[0];
    const void*  ei    = d_in[1];
    const void*  batch = d_in[2];
    const float* l0_W1   = (const float*)d_in[3];
    const float* l0_b1   = (const float*)d_in[4];
    const float* l0_W2   = (const float*)d_in[5];
    const float* l0_b2   = (const float*)d_in[6];
    const float* l0_Wres = (const float*)d_in[7];
    const float* Ws1 = (const float*)d_in[8];
    const float* bs1 = (const float*)d_in[9];
    const float* Ws2 = (const float*)d_in[10];
    const float* bs2 = (const float*)d_in[11];
    const float* fW1 = (const float*)d_in[12];
    const float* fb1 = (const float*)d_in[13];
    const float* fW2 = (const float*)d_in[14];
    const float* fb2 = (const float*)d_in[15];
    float* out = (float*)d_out;

    float *agg, *h;
    int *eiI, *batchI;
    cudaGetSymbolAddress((void**)&agg, g_agg);
    cudaGetSymbolAddress((void**)&h, g_h);
    cudaGetSymbolAddress((void**)&eiI, g_ei);
    cudaGetSymbolAddress((void**)&batchI, g_batch);

    const int DSM_L0 = 3 * 128 * LDA * 4;   // 202752
    const int DSM    = 2 * 128 * LDA * 4;   // 135168
    static bool attr_set = false;
    if (!attr_set) {
        cudaFuncSetAttribute(gin_wmma<64, true, false>,   cudaFuncAttributeMaxDynamicSharedMemorySize, DSM_L0);
        cudaFuncSetAttribute(gin_wmma<128, false, true>,  cudaFuncAttributeMaxDynamicSharedMemorySize, DSM);
        cudaFuncSetAttribute(gin_wmma<128, false, false>, cudaFuncAttributeMaxDynamicSharedMemorySize, DSM);
        attr_set = true;
    }

    // ---- index conversion ----
    detect_dtype<<<1, 256>>>((const int*)ei);
    convert_idx<<<(2 * NE + 255) / 256, 256>>>(ei, eiI, 2 * NE);
    convert_idx<<<(NN + 255) / 256, 256>>>(batch, batchI, NN);

    const int blocks = (NN + 127) / 128;  // 391

    // ---- layer 0 (64 -> 128, on-chip residual projection) ----
    copy_f4<<<(NN * IND / 4 + 255) / 256, 256>>>(x, agg, NN * IND / 4);
    scatter_add<IND><<<(NE * (IND / 4) + 255) / 256, 256>>>(x);
    gin_wmma<64, true, false><<<blocks, 256, DSM_L0>>>(
        agg, l0_W1, l0_b1, l0_W2, l0_b2, l0_Wres, x, h, nullptr);

    // ---- layers 1..3 (128 -> 128, identity residual) ----
    copy_f4<<<(NN * HD / 4 + 255) / 256, 256>>>(h, agg, NN * HD / 4);
    for (int i = 0; i < 3; i++) {
        scatter_add<HD><<<(NE * (HD / 4) + 255) / 256, 256>>>(h);
        const float* W1 = Ws1 + (size_t)i * HD * HD;
        const float* B1 = bs1 + (size_t)i * HD;
        const float* W2 = Ws2 + (size_t)i * HD * HD;
        const float* B2 = bs2 + (size_t)i * HD;
        if (i < 2)
            gin_wmma<128, false, true><<<blocks, 256, DSM>>>(agg, W1, B1, W2, B2, nullptr, h, h, agg);
        else
            gin_wmma<128, false, false><<<blocks, 256, DSM>>>(agg, W1, B1, W2, B2, nullptr, h, h, nullptr);
    }

    // ---- pool + head ----
    zero_pool<<<(NG * HD + 255) / 256, 256>>>();
    pool_accum<<<(NN * 32 + 255) / 256, 256>>>();
    head_kernel<<<NG, 128>>>(fW1, fb1, fW2, fb2, out);
}